// round 12
// baseline (speedup 1.0000x reference)
#include <cuda_runtime.h>
#include <cstdint>

// CutOutput: per-row (8192 rows) stable descending argsort of D=1571 fp32,
// out[row][r] = (float)index_at_rank_r if r < len else 0, len = base[row].
// Output float32. Stability via packed-u64 (kk<<11)|idx tie-break.
//
// R12 (issue-bound, ~3x control-overhead fat vs ideal instr count):
//  * Hand-peeled loops: iters 0..2 are provably in-bounds (t+1024 <= 1535 < D)
//    -> unconditional; only iter 3 guarded (t < 35). Kills per-iter
//    predicates + BSSY/BSYNC divergence frames in 3 hot loops.
//  * Phase-2 cnt==2 fast path: peer slot = s + (ord^1), one LDS + one cmp
//    instead of a divergent loop.
//  * Retains: len-aware bucket pruning, atomic pruning w/ exact fallback,
//    packed octave table, vectorized smem clear/scan/output.

static constexpr int D = 1571;
static constexpr int NB = 2048;
static constexpr int THREADS = 512;
static constexpr int NE = 512;       // octave-table entries (e = kk>>23)
static constexpr int TAIL = D - 3 * THREADS;  // 35: threads with a 4th element

__device__ unsigned g_pack[NE];  // per-octave: b0 | (span << 16)

__global__ void build_base_kernel() {
  const int t = threadIdx.x;
  if (t < NE) {
    auto edge = [](unsigned tt) -> unsigned {
      if (tt >= NE) return NB;
      const unsigned kk0 = tt << 23;
      const unsigned a = ~kk0;
      const unsigned u = (a & 0x80000000u) ? (a ^ 0x80000000u) : ~a;
      const float x = __uint_as_float(u);
      const float c = 0.5f * erfcf(x * 0.70710678118f);  // P(N(0,1) > x)
      unsigned b = (unsigned)(c * (float)NB);
      return b > (NB - 1u) ? (NB - 1u) : b;
    };
    const unsigned b0 = edge(t);
    const unsigned b1 = edge(t + 1);
    g_pack[t] = b0 | ((b1 - b0) << 16);
  }
}

__global__ void __launch_bounds__(THREADS) cutoutput_bucket_kernel(
    const float* __restrict__ to_cut,
    const int* __restrict__ candA,
    const int* __restrict__ candB,
    float* __restrict__ out) {
  __shared__ unsigned long long data[D];        // bucketed (kk<<11)|idx
  __shared__ unsigned pbase[NE];                // packed octave table
  __shared__ alignas(16) unsigned startb[NB + 4];
  __shared__ alignas(16) unsigned hist[NB];
  __shared__ unsigned wsum[16];
  __shared__ alignas(16) float staged[D + 1];   // rank -> (float)idx

  const int t = threadIdx.x;
  const int row = blockIdx.x;
  const float* __restrict__ src = to_cut + (size_t)row * D;

  // base vs ids disambiguation: ids[0] == 0 always; base[0] >= 1 always.
  const int* __restrict__ basep = (candA[0] == 0) ? candB : candA;
  const unsigned len = (unsigned)basep[row];

  // Atomic-pruning threshold (~7 sigma margin; verified exactly below).
  unsigned T = (unsigned)(((unsigned long long)(len + 160u) * NB) / D + 1u);
  if (T > NB) T = NB;

  // ---- copy table; clear histogram (one STS.128) ----
  if (t < NE) pbase[t] = g_pack[t];
  reinterpret_cast<uint4*>(hist)[t] = make_uint4(0u, 0u, 0u, 0u);
  __syncthreads();

  // ---- phase 1: load, key, bucket; histogram atomic ONLY for bk < T ----
  unsigned kks[4];
  unsigned short bks[4];
  unsigned short ords[4];
  auto phase1 = [&](int k, int v) {
    const unsigned u = __float_as_uint(src[v]);
    const unsigned a = u ^ ((u & 0x80000000u) ? 0xFFFFFFFFu : 0x80000000u);
    const unsigned kk = ~a;                     // ascending kk == desc value
    const unsigned pk = pbase[kk >> 23];
    const unsigned b0 = pk & 0xFFFFu;
    const unsigned n = pk >> 16;
    const unsigned m = (kk >> 7) & 0xFFFFu;
    const unsigned bk = b0 + ((m * n) >> 16);   // exact monotone in kk
    kks[k] = kk;
    bks[k] = (unsigned short)bk;
    ords[k] = (bk < T) ? (unsigned short)atomicAdd(&hist[bk], 1u)
                       : (unsigned short)0;
  };
  phase1(0, t);
  phase1(1, t + THREADS);
  phase1(2, t + 2 * THREADS);
  if (t < TAIL) phase1(3, t + 3 * THREADS);
  __syncthreads();

  // ---- scan (vectorized) + exact verification of pruning ----
  for (int attempt = 0; attempt < 2; ++attempt) {
    {
      const uint4 h4 = reinterpret_cast<const uint4*>(hist)[t];
      const unsigned sum = h4.x + h4.y + h4.z + h4.w;
      unsigned v = sum;
#pragma unroll
      for (int d = 1; d < 32; d <<= 1) {
        unsigned nbr = __shfl_up_sync(0xFFFFFFFFu, v, d);
        if ((t & 31) >= d) v += nbr;
      }
      if ((t & 31) == 31) wsum[t >> 5] = v;
      __syncthreads();
      if (t < 16) {
        unsigned w = wsum[t];
#pragma unroll
        for (int d = 1; d < 16; d <<= 1) {
          unsigned nbr = __shfl_up_sync(0xFFFFu, w, d);
          if (t >= d) w += nbr;
        }
        wsum[t] = w;
      }
      __syncthreads();
      const unsigned excl = v - sum + ((t >= 32) ? wsum[(t >> 5) - 1] : 0u);
      reinterpret_cast<uint4*>(startb)[t] =
          make_uint4(excl, excl + h4.x, excl + h4.x + h4.y,
                     excl + h4.x + h4.y + h4.z);
      if (t == THREADS - 1) startb[NB] = excl + sum;
    }
    __syncthreads();

    if (T >= NB || startb[T] >= len) break;  // pruning proven exact

    // Fallback (prob ~0): count the skipped elements, rescan with T = NB.
    auto late = [&](int k) {
      if (bks[k] >= T) ords[k] = (unsigned short)atomicAdd(&hist[bks[k]], 1u);
    };
    late(0);
    late(1);
    late(2);
    if (t < TAIL) late(3);
    T = NB;
    __syncthreads();
  }

  // ---- scatter: only LIVE buckets (startb < len); singleton fast path ----
  auto scatter = [&](int k, int v) {
    const unsigned bk = bks[k];
    const unsigned s = startb[bk];
    if (s >= len) {
      bks[k] = 0xFFFFu;                    // dead bucket: output is 0 anyway
    } else if (hist[bk] == 1u) {
      staged[s] = (float)v;                // rank known: bucket of one
      bks[k] = 0xFFFFu;
    } else {
      data[s + ords[k]] = ((unsigned long long)kks[k] << 11) | (unsigned)v;
    }
  };
  scatter(0, t);
  scatter(1, t + THREADS);
  scatter(2, t + 2 * THREADS);
  if (t < TAIL) scatter(3, t + 3 * THREADS);
  __syncthreads();

  // ---- phase 2: rank within live multi-element buckets ----
  auto rank = [&](int k, int v) {
    if (bks[k] == 0xFFFFu) return;
    const unsigned bk = bks[k];
    const unsigned s = startb[bk];
    const unsigned cnt = hist[bk];
    const unsigned long long ki =
        ((unsigned long long)kks[k] << 11) | (unsigned)v;
    unsigned r;
    if (cnt == 2u) {
      // peer slot is the one I didn't take: ord ^ 1
      const unsigned long long peer = data[s + (ords[k] ^ 1u)];
      r = s + ((peer < ki) ? 1u : 0u);
    } else {
      r = s;
      const unsigned e = s + cnt;
      for (unsigned j = s; j < e; ++j) r += (data[j] < ki) ? 1u : 0u;
    }
    if (r < len) staged[r] = (float)v;
  };
  rank(0, t);
  rank(1, t + THREADS);
  rank(2, t + 2 * THREADS);
  if (t < TAIL) rank(3, t + 3 * THREADS);
  __syncthreads();

  // ---- output: float4 staged read, masked scalar stores (row base only
  //      4B-aligned in gmem, so no STG.128) ----
  float* __restrict__ dst = out + (size_t)row * D;
  {
    const unsigned r0 = 4u * (unsigned)t;
    if (r0 < D) {
      const float4 sv = reinterpret_cast<const float4*>(staged)[t];
      const float o0 = (r0 < len) ? sv.x : 0.0f;
      const float o1 = (r0 + 1 < len) ? sv.y : 0.0f;
      const float o2 = (r0 + 2 < len) ? sv.z : 0.0f;
      const float o3 = (r0 + 3 < len) ? sv.w : 0.0f;
      dst[r0] = o0;
      if (r0 + 1 < D) dst[r0 + 1] = o1;
      if (r0 + 2 < D) dst[r0 + 2] = o2;
      if (r0 + 3 < D) dst[r0 + 3] = o3;
    }
  }
}

extern "C" void kernel_launch(void* const* d_in, const int* in_sizes, int n_in,
                              void* d_out, int out_size) {
  // to_cut is the (unique) large buffer: P*T*D elements.
  int imax = 0;
  for (int i = 1; i < n_in; ++i)
    if (in_sizes[i] > in_sizes[imax]) imax = i;
  const float* to_cut = (const float*)d_in[imax];

  int others[2], k = 0;
  for (int i = 0; i < n_in && k < 2; ++i)
    if (i != imax) others[k++] = i;
  const int* candA = (const int*)d_in[others[0]];
  const int* candB = (const int*)d_in[others[1]];

  float* out = (float*)d_out;
  const int rows = in_sizes[imax] / D;  // P*T = 8192

  build_base_kernel<<<1, NE>>>();
  cutoutput_bucket_kernel<<<rows, THREADS>>>(to_cut, candA, candB, out);
}

// round 13
// speedup vs baseline: 1.0994x; 1.0994x over previous
#include <cuda_runtime.h>
#include <cstdint>

// CutOutput: per-row (8192 rows) stable descending argsort of D=1571 fp32,
// out[row][r] = (float)index_at_rank_r if r < len else 0, len = base[row].
// Output float32. Stability via packed-u64 (kk<<11)|idx tie-break.
//
// R13 = R11 (best: 84.7us, 32 regs, occ 93.5%) + ONE isolated delta:
//  * phase-2 cnt==2 fast path (peer slot = s + (ord^1)): one LDS.64 + cmp
//    instead of a loop, on the most common live multi-bucket case.
//  * __launch_bounds__(512, 4): pin to the 32-reg / 4-block RF boundary
//    (R12 lesson: 40 regs -> 3 blocks -> +12us; 512*32*4 = 64K = whole RF).
// Retains: len-aware bucket pruning, atomic pruning w/ exact fallback,
// packed octave table, vectorized smem clear/scan/output.

static constexpr int D = 1571;
static constexpr int NB = 2048;
static constexpr int THREADS = 512;
static constexpr int NE = 512;  // octave-table entries (e = kk>>23, 9 bits)

__device__ unsigned g_pack[NE];  // per-octave: b0 | (span << 16)

__global__ void build_base_kernel() {
  const int t = threadIdx.x;
  if (t < NE) {
    auto edge = [](unsigned tt) -> unsigned {
      if (tt >= NE) return NB;
      const unsigned kk0 = tt << 23;
      const unsigned a = ~kk0;
      const unsigned u = (a & 0x80000000u) ? (a ^ 0x80000000u) : ~a;
      const float x = __uint_as_float(u);
      const float c = 0.5f * erfcf(x * 0.70710678118f);  // P(N(0,1) > x)
      unsigned b = (unsigned)(c * (float)NB);
      return b > (NB - 1u) ? (NB - 1u) : b;
    };
    const unsigned b0 = edge(t);
    const unsigned b1 = edge(t + 1);
    g_pack[t] = b0 | ((b1 - b0) << 16);
  }
}

__global__ void __launch_bounds__(THREADS, 4) cutoutput_bucket_kernel(
    const float* __restrict__ to_cut,
    const int* __restrict__ candA,
    const int* __restrict__ candB,
    float* __restrict__ out) {
  __shared__ unsigned long long data[D];        // bucketed (kk<<11)|idx
  __shared__ unsigned pbase[NE];                // packed octave table
  __shared__ alignas(16) unsigned startb[NB + 4];
  __shared__ alignas(16) unsigned hist[NB];
  __shared__ unsigned wsum[16];
  __shared__ alignas(16) float staged[D + 1];   // rank -> (float)idx

  const int t = threadIdx.x;
  const int row = blockIdx.x;
  const float* __restrict__ src = to_cut + (size_t)row * D;

  // base vs ids disambiguation: ids[0] == 0 always; base[0] >= 1 always.
  const int* __restrict__ basep = (candA[0] == 0) ? candB : candA;
  const unsigned len = (unsigned)basep[row];

  // Atomic-pruning threshold (~7 sigma margin; verified exactly below).
  unsigned T = (unsigned)(((unsigned long long)(len + 160u) * NB) / D + 1u);
  if (T > NB) T = NB;

  // ---- copy table; clear histogram (one STS.128) ----
  if (t < NE) pbase[t] = g_pack[t];
  reinterpret_cast<uint4*>(hist)[t] = make_uint4(0u, 0u, 0u, 0u);
  __syncthreads();

  // ---- phase 1: load, key, bucket; histogram atomic ONLY for bk < T ----
  unsigned kks[4];
  unsigned short bks[4];
  unsigned short ords[4];
#pragma unroll
  for (int k = 0; k < 4; ++k) {
    const int v = t + k * THREADS;
    if (v < D) {
      const unsigned u = __float_as_uint(src[v]);
      const unsigned a = u ^ ((u & 0x80000000u) ? 0xFFFFFFFFu : 0x80000000u);
      const unsigned kk = ~a;                     // ascending kk == desc value
      const unsigned pk = pbase[kk >> 23];
      const unsigned b0 = pk & 0xFFFFu;
      const unsigned n = pk >> 16;
      const unsigned m = (kk >> 7) & 0xFFFFu;
      const unsigned bk = b0 + ((m * n) >> 16);   // exact monotone in kk
      kks[k] = kk;
      bks[k] = (unsigned short)bk;
      ords[k] = (bk < T) ? (unsigned short)atomicAdd(&hist[bk], 1u)
                         : (unsigned short)0;
    }
  }
  __syncthreads();

  // ---- scan (vectorized) + exact verification of pruning ----
  for (int attempt = 0; attempt < 2; ++attempt) {
    {
      const uint4 h4 = reinterpret_cast<const uint4*>(hist)[t];
      const unsigned sum = h4.x + h4.y + h4.z + h4.w;
      unsigned v = sum;
#pragma unroll
      for (int d = 1; d < 32; d <<= 1) {
        unsigned nbr = __shfl_up_sync(0xFFFFFFFFu, v, d);
        if ((t & 31) >= d) v += nbr;
      }
      if ((t & 31) == 31) wsum[t >> 5] = v;
      __syncthreads();
      if (t < 16) {
        unsigned w = wsum[t];
#pragma unroll
        for (int d = 1; d < 16; d <<= 1) {
          unsigned nbr = __shfl_up_sync(0xFFFFu, w, d);
          if (t >= d) w += nbr;
        }
        wsum[t] = w;
      }
      __syncthreads();
      const unsigned excl = v - sum + ((t >= 32) ? wsum[(t >> 5) - 1] : 0u);
      reinterpret_cast<uint4*>(startb)[t] =
          make_uint4(excl, excl + h4.x, excl + h4.x + h4.y,
                     excl + h4.x + h4.y + h4.z);
      if (t == THREADS - 1) startb[NB] = excl + sum;
    }
    __syncthreads();

    if (T >= NB || startb[T] >= len) break;  // pruning proven exact

    // Fallback (prob ~0): count the skipped elements, rescan with T = NB.
#pragma unroll
    for (int k = 0; k < 4; ++k) {
      const int v = t + k * THREADS;
      if (v < D && bks[k] >= T) {
        ords[k] = (unsigned short)atomicAdd(&hist[bks[k]], 1u);
      }
    }
    T = NB;
    __syncthreads();
  }

  // ---- scatter: only LIVE buckets (startb < len); singleton fast path ----
#pragma unroll
  for (int k = 0; k < 4; ++k) {
    const int v = t + k * THREADS;
    if (v < D) {
      const unsigned bk = bks[k];
      const unsigned s = startb[bk];
      if (s >= len) {
        bks[k] = 0xFFFFu;                  // dead bucket: output is 0 anyway
      } else if (hist[bk] == 1u) {
        staged[s] = (float)v;              // rank known: bucket of one
        bks[k] = 0xFFFFu;
      } else {
        data[s + ords[k]] = ((unsigned long long)kks[k] << 11) | (unsigned)v;
      }
    }
  }
  __syncthreads();

  // ---- phase 2: per-element rank within live multi-element buckets ----
#pragma unroll
  for (int k = 0; k < 4; ++k) {
    const int v = t + k * THREADS;
    if (v < D && bks[k] != 0xFFFFu) {
      const unsigned bk = bks[k];
      const unsigned s = startb[bk];
      const unsigned cnt = hist[bk];
      const unsigned long long ki =
          ((unsigned long long)kks[k] << 11) | (unsigned)v;
      unsigned r = s;
      if (cnt == 2u) {
        // peer slot is the one I didn't take: ord ^ 1
        r += (data[s + (ords[k] ^ 1u)] < ki) ? 1u : 0u;
      } else {
        const unsigned e = s + cnt;
        for (unsigned j = s; j < e; ++j) r += (data[j] < ki) ? 1u : 0u;
      }
      if (r < len) staged[r] = (float)v;
    }
  }
  __syncthreads();

  // ---- output: float4 staged read, masked scalar stores (row base only
  //      4B-aligned in gmem, so no STG.128) ----
  float* __restrict__ dst = out + (size_t)row * D;
  {
    const unsigned r0 = 4u * (unsigned)t;
    if (r0 < D) {
      const float4 sv = reinterpret_cast<const float4*>(staged)[t];
      const float o0 = (r0 < len) ? sv.x : 0.0f;
      const float o1 = (r0 + 1 < len) ? sv.y : 0.0f;
      const float o2 = (r0 + 2 < len) ? sv.z : 0.0f;
      const float o3 = (r0 + 3 < len) ? sv.w : 0.0f;
      dst[r0] = o0;
      if (r0 + 1 < D) dst[r0 + 1] = o1;
      if (r0 + 2 < D) dst[r0 + 2] = o2;
      if (r0 + 3 < D) dst[r0 + 3] = o3;
    }
  }
}

extern "C" void kernel_launch(void* const* d_in, const int* in_sizes, int n_in,
                              void* d_out, int out_size) {
  // to_cut is the (unique) large buffer: P*T*D elements.
  int imax = 0;
  for (int i = 1; i < n_in; ++i)
    if (in_sizes[i] > in_sizes[imax]) imax = i;
  const float* to_cut = (const float*)d_in[imax];

  int others[2], k = 0;
  for (int i = 0; i < n_in && k < 2; ++i)
    if (i != imax) others[k++] = i;
  const int* candA = (const int*)d_in[others[0]];
  const int* candB = (const int*)d_in[others[1]];

  float* out = (float*)d_out;
  const int rows = in_sizes[imax] / D;  // P*T = 8192

  build_base_kernel<<<1, NE>>>();
  cutoutput_bucket_kernel<<<rows, THREADS>>>(to_cut, candA, candB, out);
}

// round 14
// speedup vs baseline: 1.1542x; 1.0499x over previous
#include <cuda_runtime.h>
#include <cstdint>

// CutOutput: per-row (8192 rows) stable descending argsort of D=1571 fp32,
// out[row][r] = (float)index_at_rank_r if r < len else 0, len = base[row].
// Output float32. Stability via packed-u64 (kk<<11)|idx tie-break.
//
// R14 = R11 (best, 84.7us) + LSU diet (ATOMS floor ~2cyc/lane is the wall;
// strip the other LSU ops sharing that unit):
//  * scatter dead-test by register compare bk >= T (no startb LDS for ~40%).
//  * scan emits packed (start | cnt<<16): one LDS in scatter AND phase 2
//    instead of two (both values < 2^16).
//  * provably-true guards dropped. cnt==2 fast path NOT reintroduced (R13
//    regression). __launch_bounds__(512,4) pins the 32-reg/4-block RF point.

static constexpr int D = 1571;
static constexpr int NB = 2048;
static constexpr int THREADS = 512;
static constexpr int NE = 512;  // octave-table entries (e = kk>>23, 9 bits)

__device__ unsigned g_pack[NE];  // per-octave: b0 | (span << 16)

__global__ void build_base_kernel() {
  const int t = threadIdx.x;
  if (t < NE) {
    auto edge = [](unsigned tt) -> unsigned {
      if (tt >= NE) return NB;
      const unsigned kk0 = tt << 23;
      const unsigned a = ~kk0;
      const unsigned u = (a & 0x80000000u) ? (a ^ 0x80000000u) : ~a;
      const float x = __uint_as_float(u);
      const float c = 0.5f * erfcf(x * 0.70710678118f);  // P(N(0,1) > x)
      unsigned b = (unsigned)(c * (float)NB);
      return b > (NB - 1u) ? (NB - 1u) : b;
    };
    const unsigned b0 = edge(t);
    const unsigned b1 = edge(t + 1);
    g_pack[t] = b0 | ((b1 - b0) << 16);
  }
}

__global__ void __launch_bounds__(THREADS, 4) cutoutput_bucket_kernel(
    const float* __restrict__ to_cut,
    const int* __restrict__ candA,
    const int* __restrict__ candB,
    float* __restrict__ out) {
  __shared__ unsigned long long data[D];        // bucketed (kk<<11)|idx
  __shared__ unsigned pbase[NE];                // packed octave table
  __shared__ alignas(16) unsigned startb[NB + 4];  // packed start | cnt<<16
  __shared__ alignas(16) unsigned hist[NB];
  __shared__ unsigned wsum[16];
  __shared__ alignas(16) float staged[D + 1];   // rank -> (float)idx

  const int t = threadIdx.x;
  const int row = blockIdx.x;
  const float* __restrict__ src = to_cut + (size_t)row * D;

  // base vs ids disambiguation: ids[0] == 0 always; base[0] >= 1 always.
  const int* __restrict__ basep = (candA[0] == 0) ? candB : candA;
  const unsigned len = (unsigned)basep[row];

  // Atomic-pruning threshold (~7 sigma margin; verified exactly below).
  unsigned T = (unsigned)(((unsigned long long)(len + 160u) * NB) / D + 1u);
  if (T > NB) T = NB;

  // ---- copy table (NE == THREADS: unconditional); clear histogram ----
  pbase[t] = g_pack[t];
  reinterpret_cast<uint4*>(hist)[t] = make_uint4(0u, 0u, 0u, 0u);
  __syncthreads();

  // ---- phase 1: load, key, bucket; histogram atomic ONLY for bk < T ----
  unsigned kks[4];
  unsigned short bks[4];
  unsigned short ords[4];
#pragma unroll
  for (int k = 0; k < 4; ++k) {
    const int v = t + k * THREADS;
    if (v < D) {
      const unsigned u = __float_as_uint(src[v]);
      const unsigned a = u ^ ((u & 0x80000000u) ? 0xFFFFFFFFu : 0x80000000u);
      const unsigned kk = ~a;                     // ascending kk == desc value
      const unsigned pk = pbase[kk >> 23];
      const unsigned b0 = pk & 0xFFFFu;
      const unsigned n = pk >> 16;
      const unsigned m = (kk >> 7) & 0xFFFFu;
      const unsigned bk = b0 + ((m * n) >> 16);   // exact monotone in kk
      kks[k] = kk;
      bks[k] = (unsigned short)bk;
      ords[k] = (bk < T) ? (unsigned short)atomicAdd(&hist[bk], 1u)
                         : (unsigned short)0;
    }
  }
  __syncthreads();

  // ---- scan (vectorized, packed start|cnt output) + prune verification ----
  for (int attempt = 0; attempt < 2; ++attempt) {
    {
      const uint4 h4 = reinterpret_cast<const uint4*>(hist)[t];
      const unsigned sum = h4.x + h4.y + h4.z + h4.w;
      unsigned v = sum;
#pragma unroll
      for (int d = 1; d < 32; d <<= 1) {
        unsigned nbr = __shfl_up_sync(0xFFFFFFFFu, v, d);
        if ((t & 31) >= d) v += nbr;
      }
      if ((t & 31) == 31) wsum[t >> 5] = v;
      __syncthreads();
      if (t < 16) {
        unsigned w = wsum[t];
#pragma unroll
        for (int d = 1; d < 16; d <<= 1) {
          unsigned nbr = __shfl_up_sync(0xFFFFu, w, d);
          if (t >= d) w += nbr;
        }
        wsum[t] = w;
      }
      __syncthreads();
      const unsigned excl = v - sum + ((t >= 32) ? wsum[(t >> 5) - 1] : 0u);
      reinterpret_cast<uint4*>(startb)[t] = make_uint4(
          excl | (h4.x << 16), (excl + h4.x) | (h4.y << 16),
          (excl + h4.x + h4.y) | (h4.z << 16),
          (excl + h4.x + h4.y + h4.z) | (h4.w << 16));
    }
    __syncthreads();

    if (T >= NB || (startb[T] & 0xFFFFu) >= len) break;  // pruning exact

    // Fallback (prob ~0): count the skipped elements, rescan with T = NB.
#pragma unroll
    for (int k = 0; k < 4; ++k) {
      const int v = t + k * THREADS;
      if (v < D && bks[k] >= T) {
        ords[k] = (unsigned short)atomicAdd(&hist[bks[k]], 1u);
      }
    }
    T = NB;
    __syncthreads();
  }

  // ---- scatter: dead test in registers; packed LDS only if bk < T ----
#pragma unroll
  for (int k = 0; k < 4; ++k) {
    const int v = t + k * THREADS;
    if (v < D) {
      const unsigned bk = bks[k];
      if (bk >= T) {
        bks[k] = 0xFFFFu;                  // pruned: provably rank >= len
      } else {
        const unsigned pc = startb[bk];    // start | cnt<<16
        const unsigned s = pc & 0xFFFFu;
        if (s >= len) {
          bks[k] = 0xFFFFu;                // dead bucket: output is 0 anyway
        } else if ((pc >> 16) == 1u) {
          staged[s] = (float)v;            // rank known: bucket of one
          bks[k] = 0xFFFFu;
        } else {
          data[s + ords[k]] = ((unsigned long long)kks[k] << 11) | (unsigned)v;
        }
      }
    }
  }
  __syncthreads();

  // ---- phase 2: per-element rank within live multi-element buckets ----
#pragma unroll
  for (int k = 0; k < 4; ++k) {
    const int v = t + k * THREADS;
    if (v < D && bks[k] != 0xFFFFu) {
      const unsigned pc = startb[bks[k]];
      const unsigned s = pc & 0xFFFFu;
      const unsigned e = s + (pc >> 16);
      const unsigned long long ki =
          ((unsigned long long)kks[k] << 11) | (unsigned)v;
      unsigned r = s;
      for (unsigned j = s; j < e; ++j) r += (data[j] < ki) ? 1u : 0u;
      if (r < len) staged[r] = (float)v;
    }
  }
  __syncthreads();

  // ---- output: float4 staged read, masked scalar stores (row base only
  //      4B-aligned in gmem, so no STG.128) ----
  float* __restrict__ dst = out + (size_t)row * D;
  {
    const unsigned r0 = 4u * (unsigned)t;
    if (r0 < D) {
      const float4 sv = reinterpret_cast<const float4*>(staged)[t];
      const float o0 = (r0 < len) ? sv.x : 0.0f;
      const float o1 = (r0 + 1 < len) ? sv.y : 0.0f;
      const float o2 = (r0 + 2 < len) ? sv.z : 0.0f;
      const float o3 = (r0 + 3 < len) ? sv.w : 0.0f;
      dst[r0] = o0;
      if (r0 + 1 < D) dst[r0 + 1] = o1;
      if (r0 + 2 < D) dst[r0 + 2] = o2;
      if (r0 + 3 < D) dst[r0 + 3] = o3;
    }
  }
}

extern "C" void kernel_launch(void* const* d_in, const int* in_sizes, int n_in,
                              void* d_out, int out_size) {
  // to_cut is the (unique) large buffer: P*T*D elements.
  int imax = 0;
  for (int i = 1; i < n_in; ++i)
    if (in_sizes[i] > in_sizes[imax]) imax = i;
  const float* to_cut = (const float*)d_in[imax];

  int others[2], k = 0;
  for (int i = 0; i < n_in && k < 2; ++i)
    if (i != imax) others[k++] = i;
  const int* candA = (const int*)d_in[others[0]];
  const int* candB = (const int*)d_in[others[1]];

  float* out = (float*)d_out;
  const int rows = in_sizes[imax] / D;  // P*T = 8192

  build_base_kernel<<<1, NE>>>();
  cutoutput_bucket_kernel<<<rows, THREADS>>>(to_cut, candA, candB, out);
}